// round 4
// baseline (speedup 1.0000x reference)
#include <cuda_runtime.h>
#include <cuda_bf16.h>
#include <cstdint>

#define NNODES 20000
#define NEDGES 160000
#define F_IN   512
#define F_HID  512
#define F_OUT  256

// ---------------- scratch (device globals; no allocation APIs allowed) -----
__device__ int   g_is64;                   // 1 if edge_index is int64, 0 if int32
__device__ int   g_deg[NNODES];            // in-degree (without self loop)
__device__ int   g_rowptr[NNODES + 1];     // CSR row pointers (by dst)
__device__ int   g_cursor[NNODES];         // fill cursors
__device__ int   g_srcs[NEDGES];           // CSR column (src) indices
__device__ __align__(16) float g_dinv[NNODES];
__device__ __align__(16) float g_h1[(size_t)NNODES * F_HID];
__device__ __align__(16) float g_a1[(size_t)NNODES * F_HID];
__device__ __align__(16) float g_h2[(size_t)NNODES * F_OUT];

// ---------------- edge index access (dtype-agnostic) ------------------------
__device__ __forceinline__ int2 edge_at(const void* ei, int e) {
    if (g_is64) {
        const long long* p = (const long long*)ei;
        return make_int2((int)p[e], (int)p[NEDGES + e]);
    } else {
        const int* p = (const int*)ei;
        return make_int2(p[e], p[NEDGES + e]);
    }
}

// If data is int64 with values < 2^31, every odd int32 word is 0 (little endian).
// If data is int32 (random indices in [0,20000)), odds are ~never all zero.
__global__ void detect_dtype_kernel(const int* ei) {
    if (threadIdx.x == 0 && blockIdx.x == 0) {
        int is64 = 1;
        for (int i = 1; i < 64; i += 2)
            if (ei[i] != 0) { is64 = 0; break; }
        g_is64 = is64;
    }
}

__global__ void zero_deg_kernel() {
    int i = blockIdx.x * blockDim.x + threadIdx.x;
    if (i < NNODES) g_deg[i] = 0;
}

__global__ void deg_count_kernel(const void* ei) {
    int e = blockIdx.x * blockDim.x + threadIdx.x;
    if (e < NEDGES) {
        int2 sd = edge_at(ei, e);
        atomicAdd(&g_deg[sd.y], 1);
    }
}

// single-block exclusive scan of g_deg -> g_rowptr / g_cursor; 1024 threads
__global__ void scan_kernel() {
    __shared__ int part[1024];
    const int T = 1024, CH = (NNODES + 1023) / 1024;   // 20
    const int t = threadIdx.x;
    const int base = t * CH;
    int s = 0;
    for (int i = 0; i < CH; i++) {
        int idx = base + i;
        if (idx < NNODES) s += g_deg[idx];
    }
    part[t] = s;
    __syncthreads();
    for (int off = 1; off < T; off <<= 1) {
        int v = (t >= off) ? part[t - off] : 0;
        __syncthreads();
        part[t] += v;
        __syncthreads();
    }
    int run = (t > 0) ? part[t - 1] : 0;  // exclusive prefix of this chunk
    for (int i = 0; i < CH; i++) {
        int idx = base + i;
        if (idx < NNODES) {
            g_rowptr[idx] = run;
            g_cursor[idx] = run;
            run += g_deg[idx];
        }
    }
    if (t == T - 1) g_rowptr[NNODES] = part[T - 1];
}

__global__ void dinv_kernel() {
    int i = blockIdx.x * blockDim.x + threadIdx.x;
    if (i < NNODES) g_dinv[i] = rsqrtf(1.0f + (float)g_deg[i]);  // +1 self loop
}

__global__ void fill_kernel(const void* ei) {
    int e = blockIdx.x * blockDim.x + threadIdx.x;
    if (e < NEDGES) {
        int2 sd = edge_at(ei, e);
        int pos = atomicAdd(&g_cursor[sd.y], 1);
        g_srcs[pos] = sd.x;
    }
}

// ---------------- SIMT fp32 GEMM: C[M,N] = A[M,K] @ B[K,N] -----------------
template <int BM, int BN, int BK, int TM, int TN>
__global__ void sgemm_kernel(const float* __restrict__ A, const float* __restrict__ B,
                             float* __restrict__ C, int M, int N, int K) {
    __shared__ float As[BK][BM];
    __shared__ float Bs[BK][BN];

    const int tid = threadIdx.x;
    const int block_row = blockIdx.y * BM;
    const int block_col = blockIdx.x * BN;

    const int a_row  = tid / (BK / 4);
    const int a_col4 = (tid % (BK / 4)) * 4;
    const int b_row  = tid / (BN / 4);
    const int b_col4 = (tid % (BN / 4)) * 4;

    const int ty = tid / (BN / TN);
    const int tx = tid % (BN / TN);

    float acc[TM][TN];
    #pragma unroll
    for (int i = 0; i < TM; i++)
        #pragma unroll
        for (int j = 0; j < TN; j++) acc[i][j] = 0.f;

    for (int k0 = 0; k0 < K; k0 += BK) {
        float4 av = make_float4(0.f, 0.f, 0.f, 0.f);
        const int gr = block_row + a_row;
        if (gr < M) av = *reinterpret_cast<const float4*>(A + (size_t)gr * K + k0 + a_col4);
        As[a_col4 + 0][a_row] = av.x;
        As[a_col4 + 1][a_row] = av.y;
        As[a_col4 + 2][a_row] = av.z;
        As[a_col4 + 3][a_row] = av.w;

        const float4 bv = *reinterpret_cast<const float4*>(
            B + (size_t)(k0 + b_row) * N + block_col + b_col4);
        *reinterpret_cast<float4*>(&Bs[b_row][b_col4]) = bv;

        __syncthreads();

        #pragma unroll
        for (int k = 0; k < BK; k++) {
            float ra[TM], rb[TN];
            #pragma unroll
            for (int i = 0; i < TM; i++) ra[i] = As[k][ty * TM + i];
            #pragma unroll
            for (int j = 0; j < TN; j++) rb[j] = Bs[k][tx * TN + j];
            #pragma unroll
            for (int i = 0; i < TM; i++)
                #pragma unroll
                for (int j = 0; j < TN; j++) acc[i][j] += ra[i] * rb[j];
        }
        __syncthreads();
    }

    #pragma unroll
    for (int i = 0; i < TM; i++) {
        const int gr = block_row + ty * TM + i;
        if (gr < M) {
            #pragma unroll
            for (int j = 0; j < TN; j += 4) {
                float4 v = make_float4(acc[i][j], acc[i][j + 1], acc[i][j + 2], acc[i][j + 3]);
                *reinterpret_cast<float4*>(C + (size_t)gr * N + block_col + tx * TN + j) = v;
            }
        }
    }
}

// ---------------- pull aggregation: one block per node ----------------------
// out[v] = relu( sum_{src in N(v)} h[src]*dinv[src]*dinv[v] + h[v]*dinv[v]^2 + b )
template <int F>
__global__ void aggregate_kernel(const float* __restrict__ h,
                                 const float* __restrict__ bias,
                                 float* __restrict__ out) {
    const int v = blockIdx.x;
    const int t = threadIdx.x;              // blockDim = F/2
    const float dv = g_dinv[v];
    const float sw = dv * dv;

    float2 hv = reinterpret_cast<const float2*>(h + (size_t)v * F)[t];
    float accx = hv.x * sw, accy = hv.y * sw;

    const int beg = g_rowptr[v];
    const int end = g_rowptr[v + 1];
    for (int j = beg; j < end; j++) {
        const int src = g_srcs[j];
        const float w = g_dinv[src] * dv;
        float2 hs = reinterpret_cast<const float2*>(h + (size_t)src * F)[t];
        accx += hs.x * w;
        accy += hs.y * w;
    }
    float2 b = reinterpret_cast<const float2*>(bias)[t];
    float2 o;
    o.x = fmaxf(accx + b.x, 0.f);
    o.y = fmaxf(accy + b.y, 0.f);
    reinterpret_cast<float2*>(out + (size_t)v * F)[t] = o;
}

// ---------------- launch ----------------------------------------------------
extern "C" void kernel_launch(void* const* d_in, const int* in_sizes, int n_in,
                              void* d_out, int out_size) {
    const float* x  = (const float*)d_in[0];
    const void*  ei = d_in[1];
    const float* W1 = (const float*)d_in[2];
    const float* b1 = (const float*)d_in[3];
    const float* W2 = (const float*)d_in[4];
    const float* b2 = (const float*)d_in[5];
    float* out = (float*)d_out;

    // --- graph preprocessing (CSR by dst) ---
    detect_dtype_kernel<<<1, 32>>>((const int*)ei);
    zero_deg_kernel<<<(NNODES + 255) / 256, 256>>>();
    deg_count_kernel<<<(NEDGES + 255) / 256, 256>>>(ei);
    scan_kernel<<<1, 1024>>>();
    dinv_kernel<<<(NNODES + 255) / 256, 256>>>();
    fill_kernel<<<(NEDGES + 255) / 256, 256>>>(ei);

    // --- layer 1 ---
    {
        dim3 grid(F_HID / 64, (NNODES + 63) / 64);
        sgemm_kernel<64, 64, 16, 4, 4><<<grid, 256>>>(x, W1, g_h1, NNODES, F_HID, F_IN);
    }
    aggregate_kernel<F_HID><<<NNODES, F_HID / 2>>>(g_h1, b1, g_a1);

    // --- layer 2 ---
    {
        dim3 grid(F_OUT / 64, (NNODES + 63) / 64);
        sgemm_kernel<64, 64, 16, 4, 4><<<grid, 256>>>(g_a1, W2, g_h2, NNODES, F_OUT, F_HID);
    }
    aggregate_kernel<F_OUT><<<NNODES, F_OUT / 2>>>(g_h2, b2, out);
}

// round 5
// speedup vs baseline: 1.1360x; 1.1360x over previous
#include <cuda_runtime.h>
#include <cuda_bf16.h>
#include <cstdint>

#define NNODES 20000
#define NEDGES 160000
#define F_IN   512
#define F_HID  512
#define F_OUT  256

// ---------------- scratch (device globals; no allocation APIs allowed) -----
__device__ int   g_is64;                   // 1 if edge_index is int64, 0 if int32
__device__ int   g_deg[NNODES];            // in-degree (without self loop)
__device__ int   g_rowptr[NNODES + 1];     // CSR row pointers (by dst)
__device__ int   g_cursor[NNODES];         // fill cursors
__device__ int   g_srcs[NEDGES];           // CSR column (src) indices
__device__ __align__(16) float g_dinv[NNODES];
__device__ __align__(16) float g_h1[(size_t)NNODES * F_HID];
__device__ __align__(16) float g_a1[(size_t)NNODES * F_HID];
__device__ __align__(16) float g_h2[(size_t)NNODES * F_OUT];

// ---------------- edge index access (dtype-agnostic) ------------------------
__device__ __forceinline__ int2 edge_at(const void* ei, int e) {
    if (g_is64) {
        const long long* p = (const long long*)ei;
        return make_int2((int)p[e], (int)p[NEDGES + e]);
    } else {
        const int* p = (const int*)ei;
        return make_int2(p[e], p[NEDGES + e]);
    }
}

// int64 little-endian with values < 2^31 -> every odd int32 word is 0.
__global__ void detect_dtype_kernel(const int* ei) {
    if (threadIdx.x == 0 && blockIdx.x == 0) {
        int is64 = 1;
        for (int i = 1; i < 64; i += 2)
            if (ei[i] != 0) { is64 = 0; break; }
        g_is64 = is64;
    }
}

__global__ void zero_deg_kernel() {
    int i = blockIdx.x * blockDim.x + threadIdx.x;
    if (i < NNODES) g_deg[i] = 0;
}

__global__ void deg_count_kernel(const void* ei) {
    int e = blockIdx.x * blockDim.x + threadIdx.x;
    if (e < NEDGES) {
        int2 sd = edge_at(ei, e);
        atomicAdd(&g_deg[sd.y], 1);
    }
}

// single-block exclusive scan of g_deg -> g_rowptr / g_cursor; 1024 threads
__global__ void scan_kernel() {
    __shared__ int part[1024];
    const int T = 1024, CH = (NNODES + 1023) / 1024;
    const int t = threadIdx.x;
    const int base = t * CH;
    int s = 0;
    for (int i = 0; i < CH; i++) {
        int idx = base + i;
        if (idx < NNODES) s += g_deg[idx];
    }
    part[t] = s;
    __syncthreads();
    for (int off = 1; off < T; off <<= 1) {
        int v = (t >= off) ? part[t - off] : 0;
        __syncthreads();
        part[t] += v;
        __syncthreads();
    }
    int run = (t > 0) ? part[t - 1] : 0;
    for (int i = 0; i < CH; i++) {
        int idx = base + i;
        if (idx < NNODES) {
            g_rowptr[idx] = run;
            g_cursor[idx] = run;
            run += g_deg[idx];
        }
    }
    if (t == T - 1) g_rowptr[NNODES] = part[T - 1];
}

__global__ void dinv_kernel() {
    int i = blockIdx.x * blockDim.x + threadIdx.x;
    if (i < NNODES) g_dinv[i] = rsqrtf(1.0f + (float)g_deg[i]);
}

__global__ void fill_kernel(const void* ei) {
    int e = blockIdx.x * blockDim.x + threadIdx.x;
    if (e < NEDGES) {
        int2 sd = edge_at(ei, e);
        int pos = atomicAdd(&g_cursor[sd.y], 1);
        g_srcs[pos] = sd.x;
    }
}

// ---------------- SIMT fp32 GEMM, 128x128x8, 8x8/thread, double-buffered ---
// C[M,N] = A[M,K] @ B[K,N]; N % 128 == 0, K % 8 == 0; M guarded.
__global__ __launch_bounds__(256, 2)
void sgemm128_kernel(const float* __restrict__ A, const float* __restrict__ B,
                     float* __restrict__ C, int M, int N, int K) {
    constexpr int BM = 128, BN = 128, BK = 8;
    __shared__ float As[2][BK][BM];   // transposed A tile
    __shared__ float Bs[2][BK][BN];

    const int tid = threadIdx.x;               // 0..255
    const int block_row = blockIdx.y * BM;
    const int block_col = blockIdx.x * BN;

    // global A: one float4 per thread from a row (128 rows x 8 k)
    const int a_row  = tid >> 1;               // 0..127
    const int a_col4 = (tid & 1) * 4;          // 0 or 4
    // global B: one float4 per thread (8 rows x 128 n)
    const int b_row  = tid >> 5;               // 0..7
    const int b_col4 = (tid & 31) * 4;

    const int ty = tid >> 4;                   // 0..15
    const int tx = tid & 15;                   // 0..15

    const int a_g_row = block_row + a_row;
    const bool a_ok = a_g_row < M;
    const float* a_ptr = A + (size_t)(a_ok ? a_g_row : 0) * K + a_col4;
    const float* b_ptr = B + (size_t)b_row * N + block_col + b_col4;

    float acc[8][8];
    #pragma unroll
    for (int i = 0; i < 8; i++)
        #pragma unroll
        for (int j = 0; j < 8; j++) acc[i][j] = 0.f;

    // prologue: tile 0 -> buffer 0
    {
        float4 av = a_ok ? *reinterpret_cast<const float4*>(a_ptr)
                         : make_float4(0.f, 0.f, 0.f, 0.f);
        float4 bv = *reinterpret_cast<const float4*>(b_ptr);
        As[0][a_col4 + 0][a_row] = av.x;
        As[0][a_col4 + 1][a_row] = av.y;
        As[0][a_col4 + 2][a_row] = av.z;
        As[0][a_col4 + 3][a_row] = av.w;
        *reinterpret_cast<float4*>(&Bs[0][b_row][b_col4]) = bv;
    }
    __syncthreads();

    const int nsteps = K / BK;
    for (int k0 = 0; k0 < nsteps; k0++) {
        const int buf = k0 & 1;
        float4 av, bv;
        const bool has_next = (k0 + 1) < nsteps;
        if (has_next) {
            const float* ap = a_ptr + (size_t)(k0 + 1) * BK;
            av = a_ok ? *reinterpret_cast<const float4*>(ap)
                      : make_float4(0.f, 0.f, 0.f, 0.f);
            bv = *reinterpret_cast<const float4*>(b_ptr + (size_t)(k0 + 1) * BK * N);
        }

        #pragma unroll
        for (int k = 0; k < BK; k++) {
            float4 ra0 = *reinterpret_cast<const float4*>(&As[buf][k][ty * 4]);
            float4 ra1 = *reinterpret_cast<const float4*>(&As[buf][k][ty * 4 + 64]);
            float4 rb0 = *reinterpret_cast<const float4*>(&Bs[buf][k][tx * 4]);
            float4 rb1 = *reinterpret_cast<const float4*>(&Bs[buf][k][tx * 4 + 64]);
            const float ra[8] = {ra0.x, ra0.y, ra0.z, ra0.w, ra1.x, ra1.y, ra1.z, ra1.w};
            const float rb[8] = {rb0.x, rb0.y, rb0.z, rb0.w, rb1.x, rb1.y, rb1.z, rb1.w};
            #pragma unroll
            for (int i = 0; i < 8; i++)
                #pragma unroll
                for (int j = 0; j < 8; j++) acc[i][j] += ra[i] * rb[j];
        }

        if (has_next) {
            const int nb = buf ^ 1;
            As[nb][a_col4 + 0][a_row] = av.x;
            As[nb][a_col4 + 1][a_row] = av.y;
            As[nb][a_col4 + 2][a_row] = av.z;
            As[nb][a_col4 + 3][a_row] = av.w;
            *reinterpret_cast<float4*>(&Bs[nb][b_row][b_col4]) = bv;
            __syncthreads();
        }
    }

    // epilogue: rows ty*4+{0..3} and 64+ty*4+{0..3}; cols tx*4 and 64+tx*4
    #pragma unroll
    for (int i = 0; i < 8; i++) {
        const int lr = (i < 4) ? (ty * 4 + i) : (64 + ty * 4 + i - 4);
        const int gr = block_row + lr;
        if (gr < M) {
            float4 v0 = make_float4(acc[i][0], acc[i][1], acc[i][2], acc[i][3]);
            float4 v1 = make_float4(acc[i][4], acc[i][5], acc[i][6], acc[i][7]);
            *reinterpret_cast<float4*>(C + (size_t)gr * N + block_col + tx * 4) = v0;
            *reinterpret_cast<float4*>(C + (size_t)gr * N + block_col + 64 + tx * 4) = v1;
        }
    }
}

// ---------------- pull aggregation: one block per node ----------------------
template <int F>
__global__ void aggregate_kernel(const float* __restrict__ h,
                                 const float* __restrict__ bias,
                                 float* __restrict__ out) {
    const int v = blockIdx.x;
    const int t = threadIdx.x;              // blockDim = F/2
    const float dv = g_dinv[v];
    const float sw = dv * dv;

    float2 hv = reinterpret_cast<const float2*>(h + (size_t)v * F)[t];
    float accx = hv.x * sw, accy = hv.y * sw;

    const int beg = g_rowptr[v];
    const int end = g_rowptr[v + 1];
    for (int j = beg; j < end; j++) {
        const int src = g_srcs[j];
        const float w = g_dinv[src] * dv;
        float2 hs = reinterpret_cast<const float2*>(h + (size_t)src * F)[t];
        accx += hs.x * w;
        accy += hs.y * w;
    }
    float2 b = reinterpret_cast<const float2*>(bias)[t];
    float2 o;
    o.x = fmaxf(accx + b.x, 0.f);
    o.y = fmaxf(accy + b.y, 0.f);
    reinterpret_cast<float2*>(out + (size_t)v * F)[t] = o;
}

// ---------------- launch ----------------------------------------------------
extern "C" void kernel_launch(void* const* d_in, const int* in_sizes, int n_in,
                              void* d_out, int out_size) {
    const float* x  = (const float*)d_in[0];
    const void*  ei = d_in[1];
    const float* W1 = (const float*)d_in[2];
    const float* b1 = (const float*)d_in[3];
    const float* W2 = (const float*)d_in[4];
    const float* b2 = (const float*)d_in[5];
    float* out = (float*)d_out;

    // --- graph preprocessing (CSR by dst) ---
    detect_dtype_kernel<<<1, 32>>>((const int*)ei);
    zero_deg_kernel<<<(NNODES + 255) / 256, 256>>>();
    deg_count_kernel<<<(NEDGES + 255) / 256, 256>>>(ei);
    scan_kernel<<<1, 1024>>>();
    dinv_kernel<<<(NNODES + 255) / 256, 256>>>();
    fill_kernel<<<(NEDGES + 255) / 256, 256>>>(ei);

    // --- layer 1: h1 = x @ W1 ---
    {
        dim3 grid(F_HID / 128, (NNODES + 127) / 128);
        sgemm128_kernel<<<grid, 256>>>(x, W1, g_h1, NNODES, F_HID, F_IN);
    }
    aggregate_kernel<F_HID><<<NNODES, F_HID / 2>>>(g_h1, b1, g_a1);

    // --- layer 2: h2 = a1 @ W2 ---
    {
        dim3 grid(F_OUT / 128, (NNODES + 127) / 128);
        sgemm128_kernel<<<grid, 256>>>(g_a1, W2, g_h2, NNODES, F_OUT, F_HID);
    }
    aggregate_kernel<F_OUT><<<NNODES, F_OUT / 2>>>(g_h2, b2, out);
}